// round 16
// baseline (speedup 1.0000x reference)
#include <cuda_runtime.h>
#include <cstdint>

// Fixed problem shapes
#define IMG_H 544
#define IMG_W 960
#define OUT_H 136
#define OUT_W 240

// Each WARP produces a 30x8 output strip (120x32 mag region) by streaming 38
// input rows, all intermediates in registers. Pair-iteration (2 rows/iter)
// + packed f32x2 (FFMA2) math for the elementwise stages (convert, v-blur).
#define TW 30

// Normalized 1D Gaussian, k=5, sigma=1.5
#define GW0 0.120078385f
#define GW1 0.233880757f
#define GW2 0.292081718f

typedef unsigned long long u64x;

__device__ __forceinline__ int reflect_idx(int i, int n) {
    if (i < 0) i = -i;
    if (i >= n) i = 2 * n - 2 - i;
    return i;
}

__device__ __forceinline__ float sqrt_approx(float x) {
    float r;
    asm("sqrt.approx.f32 %0, %1;" : "=f"(r) : "f"(x));
    return r;
}

__device__ __forceinline__ u64x pk2(float lo, float hi) {
    u64x r; asm("mov.b64 %0, {%1, %2};" : "=l"(r) : "f"(lo), "f"(hi)); return r;
}
__device__ __forceinline__ void upk2(float& lo, float& hi, u64x v) {
    asm("mov.b64 {%0, %1}, %2;" : "=f"(lo), "=f"(hi) : "l"(v));
}
__device__ __forceinline__ u64x fma2(u64x a, u64x b, u64x c) {
    u64x d; asm("fma.rn.f32x2 %0, %1, %2, %3;" : "=l"(d) : "l"(a), "l"(b), "l"(c)); return d;
}
__device__ __forceinline__ u64x mul2(u64x a, u64x b) {
    u64x d; asm("mul.rn.f32x2 %0, %1, %2;" : "=l"(d) : "l"(a), "l"(b)); return d;
}

__global__ __launch_bounds__(64, 7)
void EdgeGuidance_47313359733145_kernel(const float* __restrict__ in,
                                        float* __restrict__ out)
{
    const int lane = threadIdx.x & 31;
    const int wid  = threadIdx.x >> 5;
    const int ct   = blockIdx.x * 2 + wid;   // column tile 0..7 (30 out cols)
    const int by   = blockIdx.y;             // row strip 0..16  (8 out rows)
    const int b    = blockIdx.z;             // batch

    const int mx0 = ct * (TW * 4);
    const int my0 = by * 32;

    const float* __restrict__ pr = in + (size_t)b * 3 * IMG_H * IMG_W;
    const float* __restrict__ pg = pr + IMG_H * IMG_W;
    const float* __restrict__ pb = pg + IMG_H * IMG_W;

    const int gx0 = mx0 - 4 + (lane << 2);
    const bool xfast = (gx0 >= 0) && (gx0 + 3 < IMG_W);
    const int rx0 = reflect_idx(gx0 + 0, IMG_W);
    const int rx1 = reflect_idx(gx0 + 1, IMG_W);
    const int rx2 = reflect_idx(gx0 + 2, IMG_W);
    const int rx3 = reflect_idx(gx0 + 3, IMG_W);

    const int gsx = mx0 - 1 + (lane << 2);
    const bool vx0 = (gsx + 0 >= 0) && (gsx + 0 < IMG_W);
    const bool vx1 = (gsx + 1 >= 0) && (gsx + 1 < IMG_W);
    const bool vx2 = (gsx + 2 < IMG_W);
    const bool vx3 = (gsx + 3 < IMG_W);

    const unsigned FULL = 0xffffffffu;

    // Packed loop-invariant constants
    const u64x CR   = pk2(0.2989f, 0.2989f);
    const u64x CG   = pk2(0.587f,  0.587f);
    const u64x CB   = pk2(0.114f,  0.114f);
    const u64x W0p  = pk2(GW0, GW0);
    const u64x W1p  = pk2(GW1, GW1);
    const u64x W2p  = pk2(GW2, GW2);
    const u64x M01  = pk2(vx0 ? 1.0f : 0.0f, vx1 ? 1.0f : 0.0f);
    const u64x M23  = pk2(vx2 ? 1.0f : 0.0f, vx3 ? 1.0f : 0.0f);

    // 2-slot PAIR ring, packed halves: [slot][row] for planes R,G,B x {01,23}
    u64x R01[2][2], R23[2][2], G01_[2][2], G23_[2][2], B01[2][2], B23[2][2];

    auto loadrow = [&](int t, int s, int j) {
        const int gy = reflect_idx(my0 - 3 + t, IMG_H);
        const int rowoff = gy * IMG_W;
        if (xfast) {
            const ulonglong2 rv = *reinterpret_cast<const ulonglong2*>(pr + rowoff + gx0);
            const ulonglong2 gv = *reinterpret_cast<const ulonglong2*>(pg + rowoff + gx0);
            const ulonglong2 bv = *reinterpret_cast<const ulonglong2*>(pb + rowoff + gx0);
            R01[s][j] = rv.x; R23[s][j] = rv.y;
            G01_[s][j] = gv.x; G23_[s][j] = gv.y;
            B01[s][j] = bv.x; B23[s][j] = bv.y;
        } else {
            R01[s][j] = pk2(pr[rowoff + rx0], pr[rowoff + rx1]);
            R23[s][j] = pk2(pr[rowoff + rx2], pr[rowoff + rx3]);
            G01_[s][j] = pk2(pg[rowoff + rx0], pg[rowoff + rx1]);
            G23_[s][j] = pk2(pg[rowoff + rx2], pg[rowoff + rx3]);
            B01[s][j] = pk2(pb[rowoff + rx0], pb[rowoff + rx1]);
            B23[s][j] = pk2(pb[rowoff + rx2], pb[rowoff + rx3]);
        }
    };
    auto loadpair = [&](int k, int s) {
        loadrow(2 * k, s, 0);
        loadrow(2 * k + 1, s, 1);
    };

    // gray (packed) + horizontal blur (scalar shuffles) of slot s sub-row j.
    // Returns h-blur row as two packed halves.
    auto gb = [&](int s, int j, u64x& H01, u64x& H23) {
        const u64x A01 = fma2(CR, R01[s][j], fma2(CG, G01_[s][j], mul2(CB, B01[s][j])));
        const u64x A23 = fma2(CR, R23[s][j], fma2(CG, G23_[s][j], mul2(CB, B23[s][j])));
        float Ax, Ay, Az, Aw;
        upk2(Ax, Ay, A01);
        upk2(Az, Aw, A23);

        const float Bx = __shfl_down_sync(FULL, Ax, 1);
        const float By = __shfl_down_sync(FULL, Ay, 1);
        const float Bz = __shfl_down_sync(FULL, Az, 1);
        const float Bw = __shfl_down_sync(FULL, Aw, 1);
        const float C0 = __shfl_down_sync(FULL, Ax, 2);

        const float o0 = fmaf(GW0, Ay, fmaf(GW1, Az, fmaf(GW2, Aw, fmaf(GW1, Bx, GW0 * By))));
        const float o1 = fmaf(GW0, Az, fmaf(GW1, Aw, fmaf(GW2, Bx, fmaf(GW1, By, GW0 * Bz))));
        const float o2 = fmaf(GW0, Aw, fmaf(GW1, Bx, fmaf(GW2, By, fmaf(GW1, Bz, GW0 * Bw))));
        const float o3 = fmaf(GW0, Bx, fmaf(GW1, By, fmaf(GW2, Bz, fmaf(GW1, Bw, GW0 * C0))));
        H01 = pk2(o0, o1);
        H23 = pk2(o2, o3);
    };

    // Packed vertical 5-tap + boundary masking -> scalar gs row (6 floats incl. shuffles)
    auto vg = [&](u64x t0a, u64x t0b, u64x t1a, u64x t1b, u64x t2a, u64x t2b,
                  u64x t3a, u64x t3b, u64x t4a, u64x t4b, int r, float* w) {
        u64x gA = fma2(W0p, t0a, fma2(W1p, t1a, fma2(W2p, t2a, fma2(W1p, t3a, mul2(W0p, t4a)))));
        u64x gB = fma2(W0p, t0b, fma2(W1p, t1b, fma2(W2p, t2b, fma2(W1p, t3b, mul2(W0p, t4b)))));
        const int gy = my0 - 1 + r;
        const bool yok = (gy >= 0) && (gy < IMG_H);
        const u64x mA = yok ? M01 : 0ull;
        const u64x mB = yok ? M23 : 0ull;
        gA = mul2(gA, mA);
        gB = mul2(gB, mB);
        upk2(w[0], w[1], gA);
        upk2(w[2], w[3], gB);
        w[4] = __shfl_down_sync(FULL, w[0], 1);
        w[5] = __shfl_down_sync(FULL, w[1], 1);
    };

    // Prologue: pairs 0,1 (rows 0..3) -> hb window; pair 2 -> ring slot 0.
    loadpair(0, 0);
    loadpair(1, 1);
    u64x hb0a, hb0b, hb1a, hb1b, hb2a, hb2b, hb3a, hb3b;
    gb(0, 0, hb0a, hb0b);
    gb(0, 1, hb1a, hb1b);
    loadpair(2, 0);                          // slot 0 free after conversion
    gb(1, 0, hb2a, hb2b);
    gb(1, 1, hb3a, hb3b);
    // Invariant entering iter p: hb0..hb3 = rows 2p..2p+3; slot p&1 holds pair p+2.

    float w0[6], w1[6];                      // gs rows 2p-2, 2p-1
    float acc = 0.0f;

    const size_t outbase = ((size_t)b * OUT_H + by * 8) * OUT_W + ct * TW + lane;

    #pragma unroll
    for (int p = 0; p <= 16; ++p) {
        const int s = p & 1;
        if (p + 3 <= 18) loadpair(p + 3, 1 - s);   // load pair p+3

        // Convert pair p+2 -> hb rows 2p+4, 2p+5 (two independent chains)
        u64x hb4a, hb4b, hb5a, hb5b;
        gb(s, 0, hb4a, hb4b);
        gb(s, 1, hb5a, hb5b);

        // Vertical Gaussian -> gs rows 2p, 2p+1 (packed, independent)
        float w2[6], w3[6];
        vg(hb0a, hb0b, hb1a, hb1b, hb2a, hb2b, hb3a, hb3b, hb4a, hb4b, 2 * p, w2);
        vg(hb1a, hb1b, hb2a, hb2b, hb3a, hb3b, hb4a, hb4b, hb5a, hb5b, 2 * p + 1, w3);

        if (p >= 1) {
            // Sobel + magnitude: mag rows 2p-2 (w0,w1,w2) and 2p-1 (w1,w2,w3)
            float cva[6], cvb[6];
            #pragma unroll
            for (int c = 0; c < 6; c++) {
                cva[c] = w0[c] + 2.0f * w1[c] + w2[c];
                cvb[c] = w1[c] + 2.0f * w2[c] + w3[c];
            }
            #pragma unroll
            for (int c = 1; c <= 4; c++) {
                const float ax = cva[c + 1] - cva[c - 1];
                const float ay = (w2[c - 1] + 2.0f * w2[c] + w2[c + 1])
                               - (w0[c - 1] + 2.0f * w0[c] + w0[c + 1]);
                const float bx = cvb[c + 1] - cvb[c - 1];
                const float by_ = (w3[c - 1] + 2.0f * w3[c] + w3[c + 1])
                                - (w1[c - 1] + 2.0f * w1[c] + w1[c + 1]);
                acc += sqrt_approx(fmaf(ax, ax, fmaf(ay, ay, 1e-6f)))
                     + sqrt_approx(fmaf(bx, bx, fmaf(by_, by_, 1e-6f)));
            }

            if ((p & 1) == 0) {              // p = 2,4,...,16: 4 mag rows complete
                const float down = acc * (1.0f / 16.0f);
                const float e = __expf(-5.0f * (down - 0.2f));
                const float sg = __fdividef(1.0f, 1.0f + e);
                if (lane < TW) {
                    out[outbase + (size_t)(p / 2 - 1) * OUT_W] = sg * sg;
                }
                acc = 0.0f;
            }
        }

        // Shift windows (register renames under full unroll)
        hb0a = hb2a; hb0b = hb2b; hb1a = hb3a; hb1b = hb3b;
        hb2a = hb4a; hb2b = hb4b; hb3a = hb5a; hb3b = hb5b;
        #pragma unroll
        for (int c = 0; c < 6; c++) { w0[c] = w2[c]; w1[c] = w3[c]; }
    }
}

extern "C" void kernel_launch(void* const* d_in, const int* in_sizes, int n_in,
                              void* d_out, int out_size)
{
    const float* in = (const float*)d_in[0];
    float* out = (float*)d_out;

    // 8 col tiles (2 warps per block) x 17 row strips x 16 batch
    dim3 grid(4, 17, 16);                    // 1088 blocks of 64 threads
    EdgeGuidance_47313359733145_kernel<<<grid, 64>>>(in, out);
}

// round 17
// speedup vs baseline: 1.3771x; 1.3771x over previous
#include <cuda_runtime.h>
#include <cuda_bf16.h>

// Fixed problem shapes
#define IMG_H 544
#define IMG_W 960
#define OUT_H 136
#define OUT_W 240

// Each WARP produces a 30x8 output strip (120x32 mag region) by streaming 38
// input rows with all intermediates in registers. PAIR-ITERATION: 17 iters,
// each handling TWO rows (load pair p+3, convert pair p+2, v-blur gs rows
// 2p/2p+1, sobel mag rows 2p-2/2p-1) for doubled ILP.
// launch_bounds(64,8): 128-reg cap (= code's natural footprint), 8 blocks/SM
// -> 1184 resident capacity >= 1088 blocks -> single wave, no tail.
#define TW 30

// Normalized 1D Gaussian, k=5, sigma=1.5
#define GW0 0.120078385f
#define GW1 0.233880757f
#define GW2 0.292081718f

__device__ __forceinline__ int reflect_idx(int i, int n) {
    if (i < 0) i = -i;
    if (i >= n) i = 2 * n - 2 - i;
    return i;
}

__device__ __forceinline__ float sqrt_approx(float x) {
    float r;
    asm("sqrt.approx.f32 %0, %1;" : "=f"(r) : "f"(x));
    return r;
}

__global__ __launch_bounds__(64, 8)
void EdgeGuidance_47313359733145_kernel(const float* __restrict__ in,
                                        float* __restrict__ out)
{
    const int lane = threadIdx.x & 31;
    const int wid  = threadIdx.x >> 5;
    const int ct   = blockIdx.x * 2 + wid;   // column tile 0..7 (30 out cols)
    const int by   = blockIdx.y;             // row strip 0..16  (8 out rows)
    const int b    = blockIdx.z;             // batch

    const int mx0 = ct * (TW * 4);
    const int my0 = by * 32;

    const float* __restrict__ pr = in + (size_t)b * 3 * IMG_H * IMG_W;
    const float* __restrict__ pg = pr + IMG_H * IMG_W;
    const float* __restrict__ pb = pg + IMG_H * IMG_W;

    const int gx0 = mx0 - 4 + (lane << 2);
    const bool xfast = (gx0 >= 0) && (gx0 + 3 < IMG_W);
    const int rx0 = reflect_idx(gx0 + 0, IMG_W);
    const int rx1 = reflect_idx(gx0 + 1, IMG_W);
    const int rx2 = reflect_idx(gx0 + 2, IMG_W);
    const int rx3 = reflect_idx(gx0 + 3, IMG_W);

    const int gsx = mx0 - 1 + (lane << 2);
    const bool vx0 = (gsx + 0 >= 0) && (gsx + 0 < IMG_W);
    const bool vx1 = (gsx + 1 >= 0) && (gsx + 1 < IMG_W);
    const bool vx2 = (gsx + 2 < IMG_W);
    const bool vx3 = (gsx + 3 < IMG_W);

    const unsigned FULL = 0xffffffffu;

    // 2-slot PAIR ring: each slot holds 2 rows x 3 planes
    float4 RB[2][2], GB[2][2], BB[2][2];

    // Load one raw row t (global reflect(my0-3+t)) into slot s, sub-row j.
    auto loadrow = [&](int t, int s, int j) {
        const int gy = reflect_idx(my0 - 3 + t, IMG_H);
        const int rowoff = gy * IMG_W;
        if (xfast) {
            RB[s][j] = *reinterpret_cast<const float4*>(pr + rowoff + gx0);
            GB[s][j] = *reinterpret_cast<const float4*>(pg + rowoff + gx0);
            BB[s][j] = *reinterpret_cast<const float4*>(pb + rowoff + gx0);
        } else {
            RB[s][j] = make_float4(pr[rowoff + rx0], pr[rowoff + rx1], pr[rowoff + rx2], pr[rowoff + rx3]);
            GB[s][j] = make_float4(pg[rowoff + rx0], pg[rowoff + rx1], pg[rowoff + rx2], pg[rowoff + rx3]);
            BB[s][j] = make_float4(pb[rowoff + rx0], pb[rowoff + rx1], pb[rowoff + rx2], pb[rowoff + rx3]);
        }
    };
    // Load pair k (rows 2k, 2k+1) into slot s.
    auto loadpair = [&](int k, int s) {
        loadrow(2 * k, s, 0);
        loadrow(2 * k + 1, s, 1);
    };

    // gray + horizontal blur of slot s sub-row j
    auto gb = [&](int s, int j) -> float4 {
        const float4 r4 = RB[s][j], g4 = GB[s][j], b4 = BB[s][j];
        float4 A;
        A.x = fmaf(0.2989f, r4.x, fmaf(0.587f, g4.x, 0.114f * b4.x));
        A.y = fmaf(0.2989f, r4.y, fmaf(0.587f, g4.y, 0.114f * b4.y));
        A.z = fmaf(0.2989f, r4.z, fmaf(0.587f, g4.z, 0.114f * b4.z));
        A.w = fmaf(0.2989f, r4.w, fmaf(0.587f, g4.w, 0.114f * b4.w));

        const float Bx = __shfl_down_sync(FULL, A.x, 1);
        const float By = __shfl_down_sync(FULL, A.y, 1);
        const float Bz = __shfl_down_sync(FULL, A.z, 1);
        const float Bw = __shfl_down_sync(FULL, A.w, 1);
        const float C0 = __shfl_down_sync(FULL, A.x, 2);

        float4 o4;
        o4.x = fmaf(GW0, A.y, fmaf(GW1, A.z, fmaf(GW2, A.w, fmaf(GW1, Bx, GW0 * By))));
        o4.y = fmaf(GW0, A.z, fmaf(GW1, A.w, fmaf(GW2, Bx, fmaf(GW1, By, GW0 * Bz))));
        o4.z = fmaf(GW0, A.w, fmaf(GW1, Bx, fmaf(GW2, By, fmaf(GW1, Bz, GW0 * Bw))));
        o4.w = fmaf(GW0, Bx, fmaf(GW1, By, fmaf(GW2, Bz, fmaf(GW1, Bw, GW0 * C0))));
        return o4;
    };

    // Vertical 5-tap from hb window rows (passed explicitly)
    auto vg = [&](const float4& t0, const float4& t1, const float4& t2,
                  const float4& t3, const float4& t4, int r) -> float4 {
        float4 g;
        g.x = fmaf(GW0, t0.x, fmaf(GW1, t1.x, fmaf(GW2, t2.x, fmaf(GW1, t3.x, GW0 * t4.x))));
        g.y = fmaf(GW0, t0.y, fmaf(GW1, t1.y, fmaf(GW2, t2.y, fmaf(GW1, t3.y, GW0 * t4.y))));
        g.z = fmaf(GW0, t0.z, fmaf(GW1, t1.z, fmaf(GW2, t2.z, fmaf(GW1, t3.z, GW0 * t4.z))));
        g.w = fmaf(GW0, t0.w, fmaf(GW1, t1.w, fmaf(GW2, t2.w, fmaf(GW1, t3.w, GW0 * t4.w))));
        const int gy = my0 - 1 + r;
        const bool yok = (gy >= 0) && (gy < IMG_H);
        g.x = (yok && vx0) ? g.x : 0.0f;
        g.y = (yok && vx1) ? g.y : 0.0f;
        g.z = (yok && vx2) ? g.z : 0.0f;
        g.w = (yok && vx3) ? g.w : 0.0f;
        return g;
    };

    // Prologue: pairs 0,1 (rows 0..3) -> hb window; pair 2 -> ring slot 0.
    loadpair(0, 0);
    loadpair(1, 1);
    float4 hb0 = gb(0, 0);
    float4 hb1 = gb(0, 1);
    loadpair(2, 0);                          // slot 0 free after conversion
    float4 hb2 = gb(1, 0);
    float4 hb3 = gb(1, 1);
    // Invariant entering iter p: hb0..hb3 = rows 2p..2p+3; slot p&1 holds pair p+2.

    float w0[6], w1[6];                      // gs rows 2p-2, 2p-1
    float acc = 0.0f;

    const size_t outbase = ((size_t)b * OUT_H + by * 8) * OUT_W + ct * TW + lane;

    #pragma unroll
    for (int p = 0; p <= 16; ++p) {
        const int s = p & 1;
        // Load pair p+3 into the other slot (holds stale pair p+1)
        if (p + 3 <= 18) loadpair(p + 3, 1 - s);

        // Convert pair p+2 -> hb rows 2p+4, 2p+5 (two independent chains)
        const float4 hb4 = gb(s, 0);
        const float4 hb5 = gb(s, 1);

        // Vertical Gaussian -> gs rows 2p, 2p+1 (independent)
        const float4 g0 = vg(hb0, hb1, hb2, hb3, hb4, 2 * p);
        const float4 g1 = vg(hb1, hb2, hb3, hb4, hb5, 2 * p + 1);

        float w2[6], w3[6];
        w2[0] = g0.x; w2[1] = g0.y; w2[2] = g0.z; w2[3] = g0.w;
        w3[0] = g1.x; w3[1] = g1.y; w3[2] = g1.z; w3[3] = g1.w;
        w2[4] = __shfl_down_sync(FULL, g0.x, 1);
        w3[4] = __shfl_down_sync(FULL, g1.x, 1);
        w2[5] = __shfl_down_sync(FULL, g0.y, 1);
        w3[5] = __shfl_down_sync(FULL, g1.y, 1);

        if (p >= 1) {
            // Sobel + magnitude: mag rows 2p-2 (w0,w1,w2) and 2p-1 (w1,w2,w3)
            float cva[6], cvb[6];
            #pragma unroll
            for (int c = 0; c < 6; c++) {
                cva[c] = w0[c] + 2.0f * w1[c] + w2[c];
                cvb[c] = w1[c] + 2.0f * w2[c] + w3[c];
            }
            #pragma unroll
            for (int c = 1; c <= 4; c++) {
                const float ax = cva[c + 1] - cva[c - 1];
                const float ay = (w2[c - 1] + 2.0f * w2[c] + w2[c + 1])
                               - (w0[c - 1] + 2.0f * w0[c] + w0[c + 1]);
                const float bx = cvb[c + 1] - cvb[c - 1];
                const float by_ = (w3[c - 1] + 2.0f * w3[c] + w3[c + 1])
                                - (w1[c - 1] + 2.0f * w1[c] + w1[c + 1]);
                acc += sqrt_approx(fmaf(ax, ax, fmaf(ay, ay, 1e-6f)))
                     + sqrt_approx(fmaf(bx, bx, fmaf(by_, by_, 1e-6f)));
            }

            if ((p & 1) == 0) {              // p = 2,4,...,16: 4 mag rows complete
                const float down = acc * (1.0f / 16.0f);
                const float e = __expf(-5.0f * (down - 0.2f));
                const float sg = __fdividef(1.0f, 1.0f + e);
                if (lane < TW) {
                    out[outbase + (size_t)(p / 2 - 1) * OUT_W] = sg * sg;
                }
                acc = 0.0f;
            }
        }

        // Shift windows (register renames under full unroll)
        hb0 = hb2; hb1 = hb3; hb2 = hb4; hb3 = hb5;
        #pragma unroll
        for (int c = 0; c < 6; c++) { w0[c] = w2[c]; w1[c] = w3[c]; }
    }
}

extern "C" void kernel_launch(void* const* d_in, const int* in_sizes, int n_in,
                              void* d_out, int out_size)
{
    const float* in = (const float*)d_in[0];
    float* out = (float*)d_out;

    // 8 col tiles (2 warps per block) x 17 row strips x 16 batch
    dim3 grid(4, 17, 16);                    // 1088 blocks of 64 threads
    EdgeGuidance_47313359733145_kernel<<<grid, 64>>>(in, out);
}